// round 4
// baseline (speedup 1.0000x reference)
#include <cuda_runtime.h>

#define BATCH 1024
#define NIN   1152
#define DIN   8
#define NOUT  10
#define DOUT  16
#define QTOT  (NIN * DIN)        // 9216
#define NCHUNK 36
#define CI     (NIN / NCHUNK)    // 32 input capsules per block
#define TB     32
#define BTILES (BATCH / TB)      // 32
#define SI     4                 // i's per W sub-tile
#define NSUB   (CI / SI)         // 8

#define WS_FLOATS (SI * NOUT * 128)      // 5120 floats per W buffer (20KB)
#define XS_FLOATS (CI * DIN * TB)        // 8192 floats (32KB)
#define SMEM_BYTES ((2 * WS_FLOATS + XS_FLOATS) * 4)   // 72KB

typedef unsigned long long u64;

// Static device scratch (no allocations allowed)
__device__ float g_xt[QTOT][BATCH];                     // x^T: [i*8+e][b]  (36 MB)
__device__ float g_Wt[NIN * NOUT * DIN * DOUT];         // W^T: [i][n][e][d] (5.9 MB)
__device__ float g_partial[NCHUNK][BATCH][NOUT][DOUT];  // 23.6 MB
__device__ float g_pden[NCHUNK][BATCH][NOUT];
__device__ float g_vsum[BATCH][NOUT][DOUT];

// ---- packed f32x2 helpers (PTX-only on sm_103a; 2x fp32 FMA throughput) ----
__device__ __forceinline__ u64 fma2(u64 a, u64 b, u64 c) {
    u64 d; asm("fma.rn.f32x2 %0,%1,%2,%3;" : "=l"(d) : "l"(a), "l"(b), "l"(c)); return d;
}
__device__ __forceinline__ u64 mul2(u64 a, u64 b) {
    u64 d; asm("mul.rn.f32x2 %0,%1,%2;" : "=l"(d) : "l"(a), "l"(b)); return d;
}
__device__ __forceinline__ u64 add2(u64 a, u64 b) {
    u64 d; asm("add.rn.f32x2 %0,%1,%2;" : "=l"(d) : "l"(a), "l"(b)); return d;
}
__device__ __forceinline__ u64 dup2(float x) {
    u64 d; asm("mov.b64 %0,{%1,%1};" : "=l"(d) : "f"(x)); return d;
}
__device__ __forceinline__ float hadd2(u64 a) {
    float lo, hi; asm("mov.b64 {%0,%1},%2;" : "=f"(lo), "=f"(hi) : "l"(a)); return lo + hi;
}

// ---- cp.async helpers ----
__device__ __forceinline__ void cpa16(void* smem_dst, const void* gmem_src) {
    unsigned s = (unsigned)__cvta_generic_to_shared(smem_dst);
    asm volatile("cp.async.cg.shared.global [%0], [%1], 16;" :: "r"(s), "l"(gmem_src));
}
__device__ __forceinline__ void cpa_commit() { asm volatile("cp.async.commit_group;"); }
template <int N> __device__ __forceinline__ void cpa_wait() {
    asm volatile("cp.async.wait_group %0;" :: "n"(N));
}

// ---- fused prep: x[b][q] -> g_xt[q][b]  AND  W[in][d][e] -> g_Wt[in][e][d] ----
#define XT_BLOCKS (QTOT / 32 * (BATCH / 32))     // 288*32 = 9216
#define WT_BLOCKS 720                             // 720 * 2048 = 1,474,560 elems
__global__ void prep(const float* __restrict__ x, const float* __restrict__ W)
{
    if (blockIdx.x < XT_BLOCKS) {
        __shared__ float t[32][33];
        const int tile = blockIdx.x;
        const int q0 = (tile % (QTOT / 32)) * 32;
        const int b0 = (tile / (QTOT / 32)) * 32;
        const int lane = threadIdx.x & 31;
        const int w = threadIdx.x >> 5;
#pragma unroll
        for (int r = w; r < 32; r += 8)
            t[r][lane] = x[(size_t)(b0 + r) * QTOT + q0 + lane];
        __syncthreads();
#pragma unroll
        for (int r = w; r < 32; r += 8)
            g_xt[q0 + r][b0 + lane] = t[lane][r];
    } else {
        const int wb = blockIdx.x - XT_BLOCKS;
#pragma unroll
        for (int k = 0; k < 8; k++) {
            const int g = wb * 2048 + k * 256 + threadIdx.x;
            const int d = g & 15;
            const int e = (g >> 4) & 7;
            const int in = g >> 7;
            g_Wt[g] = W[(size_t)in * 128 + d * 8 + e];
        }
    }
}

// ---- One routing pass: x and W both staged in smem; all d-math packed f32x2 ----
template <bool FIRST>
__global__ void __launch_bounds__(TB * NOUT, 2)
route_pass()
{
    extern __shared__ float sm[];
    float* ws0 = sm;                       // W buffers [2][SI*NOUT*128]
    float* xs  = sm + 2 * WS_FLOATS;       // x tile [CI*8][TB]

    const int tid  = threadIdx.x;
    const int n    = tid >> 5;
    const int lane = tid & 31;
    const int b    = blockIdx.y * TB + lane;
    const int i0   = blockIdx.x * CI;

    // ---- stage x tile: rows (i_local*8+e) of 32 floats from g_xt ----
    {
        const float* src = &g_xt[i0 * DIN][0] + blockIdx.y * TB;
#pragma unroll
        for (int k = 0; k < 7; k++) {
            const int idx = tid + k * 320;            // 16B unit over 2048
            if (idx < CI * DIN * 8 / 4 * 2) { }       // (compile-time noop)
            if (idx < 2048) {
                const int row = idx >> 3, off = idx & 7;
                cpa16(xs + row * 32 + off * 4,
                      src + (size_t)row * BATCH + off * 4);
            }
        }
    }
    // ---- prefetch W sub-tile 0 ----
    const float* __restrict__ wbase = g_Wt + (size_t)i0 * NOUT * 128;
#pragma unroll
    for (int k = 0; k < 4; k++)
        cpa16(ws0 + (tid + k * 320) * 4, wbase + (size_t)(tid + k * 320) * 4);
    cpa_commit();

    u64 vs2[8];
    if (!FIRST) {
        const ulonglong2* vp = reinterpret_cast<const ulonglong2*>(&g_vsum[b][n][0]);
#pragma unroll
        for (int k = 0; k < 4; k++) { ulonglong2 t = vp[k]; vs2[2*k] = t.x; vs2[2*k+1] = t.y; }
    }

    u64 acc2[8];
#pragma unroll
    for (int k = 0; k < 8; k++) acc2[k] = 0ull;
    float accd = 0.0f;

    for (int s = 0; s < NSUB; s++) {
        if (s + 1 < NSUB) {
            float* dst = ws0 + ((s + 1) & 1) * WS_FLOATS;
            const float* src = wbase + (size_t)(s + 1) * WS_FLOATS;
#pragma unroll
            for (int k = 0; k < 4; k++)
                cpa16(dst + (tid + k * 320) * 4, src + (size_t)(tid + k * 320) * 4);
            cpa_commit();
            cpa_wait<1>();
        } else {
            cpa_wait<0>();
        }
        __syncthreads();

        const ulonglong2* __restrict__ wsb =
            reinterpret_cast<const ulonglong2*>(ws0 + (s & 1) * WS_FLOATS);
        const float* __restrict__ xsb = xs + s * SI * DIN * TB;

#pragma unroll 2
        for (int ii = 0; ii < SI; ii++) {
            float xv[8];
#pragma unroll
            for (int e = 0; e < 8; e++) xv[e] = xsb[(ii * DIN + e) * TB + lane];

            const ulonglong2* __restrict__ wp = wsb + (ii * NOUT + n) * 32;

            u64 u2[8];
#pragma unroll
            for (int e = 0; e < 8; e++) {
                const u64 xd = dup2(xv[e]);
                const ulonglong2 w0 = wp[e * 4 + 0];
                const ulonglong2 w1 = wp[e * 4 + 1];
                const ulonglong2 w2 = wp[e * 4 + 2];
                const ulonglong2 w3 = wp[e * 4 + 3];
                if (e == 0) {
                    u2[0] = mul2(xd, w0.x); u2[1] = mul2(xd, w0.y);
                    u2[2] = mul2(xd, w1.x); u2[3] = mul2(xd, w1.y);
                    u2[4] = mul2(xd, w2.x); u2[5] = mul2(xd, w2.y);
                    u2[6] = mul2(xd, w3.x); u2[7] = mul2(xd, w3.y);
                } else {
                    u2[0] = fma2(xd, w0.x, u2[0]); u2[1] = fma2(xd, w0.y, u2[1]);
                    u2[2] = fma2(xd, w1.x, u2[2]); u2[3] = fma2(xd, w1.y, u2[3]);
                    u2[4] = fma2(xd, w2.x, u2[4]); u2[5] = fma2(xd, w2.y, u2[5]);
                    u2[6] = fma2(xd, w3.x, u2[6]); u2[7] = fma2(xd, w3.y, u2[7]);
                }
            }

            if (FIRST) {
#pragma unroll
                for (int k = 0; k < 8; k++) acc2[k] = add2(acc2[k], u2[k]);
            } else {
                u64 l2 = mul2(u2[0], vs2[0]);
#pragma unroll
                for (int k = 1; k < 8; k++) l2 = fma2(u2[k], vs2[k], l2);
                const float wgt = __expf(hadd2(l2));  // logits O(10): no max-shift needed
                const u64 wd = dup2(wgt);
#pragma unroll
                for (int k = 0; k < 8; k++) acc2[k] = fma2(wd, u2[k], acc2[k]);
                accd += wgt;
            }
        }
        __syncthreads();   // all warps done with buf[s&1] before refill at s+1
    }

    ulonglong2* pp = reinterpret_cast<ulonglong2*>(&g_partial[blockIdx.x][b][n][0]);
    pp[0] = make_ulonglong2(acc2[0], acc2[1]);
    pp[1] = make_ulonglong2(acc2[2], acc2[3]);
    pp[2] = make_ulonglong2(acc2[4], acc2[5]);
    pp[3] = make_ulonglong2(acc2[6], acc2[7]);
    g_pden[blockIdx.x][b][n] = FIRST ? (float)CI : accd;
}

// ---- Reduce partials, squash, update Vsum / write output ----
template <bool FIRST, bool LAST>
__global__ void __launch_bounds__(NOUT * DOUT)
squash_update(float* __restrict__ out)
{
    const int b = blockIdx.x;
    const int tid = threadIdx.x;
    const int n = tid >> 4;
    const int d = tid & 15;

    float num = 0.0f;
#pragma unroll
    for (int c = 0; c < NCHUNK; c++) num += g_partial[c][b][n][d];
    float den = 0.0f;
#pragma unroll
    for (int c = 0; c < NCHUNK; c++) den += g_pden[c][b][n];

    const float s = num / den;

    float s2 = s * s;
#pragma unroll
    for (int off = 8; off; off >>= 1) s2 += __shfl_xor_sync(0xffffffffu, s2, off);

    const float scale = s2 / (1.0f + s2) * rsqrtf(s2 + 1e-7f);
    const float v = scale * s;

    if (LAST)       out[((size_t)b * NOUT + n) * DOUT + d] = v;
    else if (FIRST) g_vsum[b][n][d] = v;
    else            g_vsum[b][n][d] += v;
}

extern "C" void kernel_launch(void* const* d_in, const int* in_sizes, int n_in,
                              void* d_out, int out_size)
{
    const float* x;
    const float* W;
    if (in_sizes[0] == BATCH * NIN * DIN) { x = (const float*)d_in[0]; W = (const float*)d_in[1]; }
    else                                  { x = (const float*)d_in[1]; W = (const float*)d_in[0]; }
    float* out = (float*)d_out;

    // opt-in >48KB dynamic smem (idempotent; host-side attribute, graph-safe)
    static bool attr_done = false;
    if (!attr_done) {
        cudaFuncSetAttribute(route_pass<true >, cudaFuncAttributeMaxDynamicSharedMemorySize, SMEM_BYTES);
        cudaFuncSetAttribute(route_pass<false>, cudaFuncAttributeMaxDynamicSharedMemorySize, SMEM_BYTES);
        attr_done = true;
    }

    prep<<<XT_BLOCKS + WT_BLOCKS, 256>>>(x, W);

    dim3 grid(NCHUNK, BTILES);
    const int threads = TB * NOUT;

    route_pass<true ><<<grid, threads, SMEM_BYTES>>>();
    squash_update<true , false><<<BATCH, NOUT * DOUT>>>(out);

    route_pass<false><<<grid, threads, SMEM_BYTES>>>();
    squash_update<false, false><<<BATCH, NOUT * DOUT>>>(out);

    route_pass<false><<<grid, threads, SMEM_BYTES>>>();   // <- ncu capture slot (launch #5)
    squash_update<false, true ><<<BATCH, NOUT * DOUT>>>(out);
}

// round 5
// speedup vs baseline: 1.0940x; 1.0940x over previous
#include <cuda_runtime.h>

#define BATCH 1024
#define NIN   1152
#define DIN   8
#define NOUT  10
#define DOUT  16
#define QTOT  (NIN * DIN)        // 9216
#define NCHUNK 36
#define CI     (NIN / NCHUNK)    // 32 input capsules per block
#define TB     64                // batches per CTA (2 per thread)
#define BTILES (BATCH / TB)      // 16
#define SI     4                 // i's per W sub-tile
#define NSUB   (CI / SI)         // 8

#define WS_FLOATS (SI * NOUT * 128)      // 5120 floats per W buffer (20KB)
#define XS_FLOATS (CI * DIN * TB)        // 16384 floats (64KB)
#define SMEM_BYTES ((2 * WS_FLOATS + XS_FLOATS) * 4)   // 104KB

typedef unsigned long long u64;

// Static device scratch (no allocations allowed)
__device__ float g_xt[QTOT][BATCH];                     // x^T: [i*8+e][b]
__device__ float g_Wt[NIN * NOUT * DIN * DOUT];         // W^T: [i][n][e][d]
__device__ float g_partial[NCHUNK][BATCH][NOUT][DOUT];
__device__ float g_pden[NCHUNK][BATCH][NOUT];
__device__ float g_vsum[BATCH][NOUT][DOUT];

// ---- packed f32x2 helpers ----
__device__ __forceinline__ u64 fma2(u64 a, u64 b, u64 c) {
    u64 d; asm("fma.rn.f32x2 %0,%1,%2,%3;" : "=l"(d) : "l"(a), "l"(b), "l"(c)); return d;
}
__device__ __forceinline__ u64 mul2(u64 a, u64 b) {
    u64 d; asm("mul.rn.f32x2 %0,%1,%2;" : "=l"(d) : "l"(a), "l"(b)); return d;
}
__device__ __forceinline__ u64 add2(u64 a, u64 b) {
    u64 d; asm("add.rn.f32x2 %0,%1,%2;" : "=l"(d) : "l"(a), "l"(b)); return d;
}
__device__ __forceinline__ u64 dup2(float x) {
    u64 d; asm("mov.b64 %0,{%1,%1};" : "=l"(d) : "f"(x)); return d;
}
__device__ __forceinline__ float hadd2(u64 a) {
    float lo, hi; asm("mov.b64 {%0,%1},%2;" : "=f"(lo), "=f"(hi) : "l"(a)); return lo + hi;
}

// ---- cp.async helpers ----
__device__ __forceinline__ void cpa16(void* smem_dst, const void* gmem_src) {
    unsigned s = (unsigned)__cvta_generic_to_shared(smem_dst);
    asm volatile("cp.async.cg.shared.global [%0], [%1], 16;" :: "r"(s), "l"(gmem_src));
}
__device__ __forceinline__ void cpa_commit() { asm volatile("cp.async.commit_group;"); }
template <int N> __device__ __forceinline__ void cpa_wait() {
    asm volatile("cp.async.wait_group %0;" :: "n"(N));
}

// ---- fused prep: x[b][q] -> g_xt[q][b]  AND  W[in][d][e] -> g_Wt[in][e][d] ----
#define XT_BLOCKS (QTOT / 32 * (BATCH / 32))
#define WT_BLOCKS 720
__global__ void prep(const float* __restrict__ x, const float* __restrict__ W)
{
    if (blockIdx.x < XT_BLOCKS) {
        __shared__ float t[32][33];
        const int tile = blockIdx.x;
        const int q0 = (tile % (QTOT / 32)) * 32;
        const int b0 = (tile / (QTOT / 32)) * 32;
        const int lane = threadIdx.x & 31;
        const int w = threadIdx.x >> 5;
#pragma unroll
        for (int r = w; r < 32; r += 8)
            t[r][lane] = x[(size_t)(b0 + r) * QTOT + q0 + lane];
        __syncthreads();
#pragma unroll
        for (int r = w; r < 32; r += 8)
            g_xt[q0 + r][b0 + lane] = t[lane][r];
    } else {
        const int wb = blockIdx.x - XT_BLOCKS;
#pragma unroll
        for (int k = 0; k < 8; k++) {
            const int g = wb * 2048 + k * 256 + threadIdx.x;
            const int d = g & 15;
            const int e = (g >> 4) & 7;
            const int in = g >> 7;
            g_Wt[g] = W[(size_t)in * 128 + d * 8 + e];
        }
    }
}

// ---- One routing pass: 2 batches per thread; x + W staged in smem; f32x2 math ----
template <bool FIRST>
__global__ void __launch_bounds__(320, 1)
route_pass()
{
    extern __shared__ float sm[];
    float* ws0 = sm;                       // W buffers [2][SI*NOUT*128]
    float* xs  = sm + 2 * WS_FLOATS;       // x tile [CI*8][TB=64]

    const int tid  = threadIdx.x;
    const int n    = tid >> 5;
    const int lane = tid & 31;
    const int bA   = blockIdx.y * TB + lane;
    const int bB   = bA + 32;
    const int i0   = blockIdx.x * CI;

    // ---- stage x tile: 256 rows x 64 floats = 4096 x 16B chunks ----
    {
        const float* src0 = &g_xt[i0 * DIN][0] + blockIdx.y * TB;
#pragma unroll
        for (int k = 0; k < 13; k++) {
            const int idx = tid + k * 320;
            if (idx < (CI * DIN) * (TB / 4)) {
                const int row = idx >> 4, off = idx & 15;   // 16 chunks per 64-float row
                cpa16(xs + row * TB + off * 4,
                      src0 + (size_t)row * BATCH + off * 4);
            }
        }
    }
    // ---- prefetch W sub-tile 0 ----
    const float* __restrict__ wbase = g_Wt + (size_t)i0 * NOUT * 128;
#pragma unroll
    for (int k = 0; k < 4; k++)
        cpa16(ws0 + (tid + k * 320) * 4, wbase + (size_t)(tid + k * 320) * 4);
    cpa_commit();

    u64 vsA[8], vsB[8];
    if (!FIRST) {
        const ulonglong2* vpA = reinterpret_cast<const ulonglong2*>(&g_vsum[bA][n][0]);
        const ulonglong2* vpB = reinterpret_cast<const ulonglong2*>(&g_vsum[bB][n][0]);
#pragma unroll
        for (int k = 0; k < 4; k++) {
            ulonglong2 tA = vpA[k]; vsA[2*k] = tA.x; vsA[2*k+1] = tA.y;
            ulonglong2 tB = vpB[k]; vsB[2*k] = tB.x; vsB[2*k+1] = tB.y;
        }
    }

    u64 accA[8], accB[8];
#pragma unroll
    for (int k = 0; k < 8; k++) { accA[k] = 0ull; accB[k] = 0ull; }
    float accdA = 0.0f, accdB = 0.0f;

    for (int s = 0; s < NSUB; s++) {
        if (s + 1 < NSUB) {
            float* dst = ws0 + ((s + 1) & 1) * WS_FLOATS;
            const float* src = wbase + (size_t)(s + 1) * WS_FLOATS;
#pragma unroll
            for (int k = 0; k < 4; k++)
                cpa16(dst + (tid + k * 320) * 4, src + (size_t)(tid + k * 320) * 4);
            cpa_commit();
            cpa_wait<1>();
        } else {
            cpa_wait<0>();
        }
        __syncthreads();

        const ulonglong2* __restrict__ wsb =
            reinterpret_cast<const ulonglong2*>(ws0 + (s & 1) * WS_FLOATS);
        const float* __restrict__ xsb = xs + s * SI * DIN * TB;

        for (int ii = 0; ii < SI; ii++) {
            const ulonglong2* __restrict__ wp = wsb + (ii * NOUT + n) * 32;

            u64 uA[8], uB[8];
#pragma unroll
            for (int e = 0; e < 8; e++) {
                const float xa = xsb[(ii * DIN + e) * TB + lane];
                const float xb = xsb[(ii * DIN + e) * TB + lane + 32];
                const u64 xdA = dup2(xa);
                const u64 xdB = dup2(xb);
                const ulonglong2 w0 = wp[e * 4 + 0];
                const ulonglong2 w1 = wp[e * 4 + 1];
                const ulonglong2 w2 = wp[e * 4 + 2];
                const ulonglong2 w3 = wp[e * 4 + 3];
                if (e == 0) {
                    uA[0] = mul2(xdA, w0.x); uA[1] = mul2(xdA, w0.y);
                    uA[2] = mul2(xdA, w1.x); uA[3] = mul2(xdA, w1.y);
                    uA[4] = mul2(xdA, w2.x); uA[5] = mul2(xdA, w2.y);
                    uA[6] = mul2(xdA, w3.x); uA[7] = mul2(xdA, w3.y);
                    uB[0] = mul2(xdB, w0.x); uB[1] = mul2(xdB, w0.y);
                    uB[2] = mul2(xdB, w1.x); uB[3] = mul2(xdB, w1.y);
                    uB[4] = mul2(xdB, w2.x); uB[5] = mul2(xdB, w2.y);
                    uB[6] = mul2(xdB, w3.x); uB[7] = mul2(xdB, w3.y);
                } else {
                    uA[0] = fma2(xdA, w0.x, uA[0]); uA[1] = fma2(xdA, w0.y, uA[1]);
                    uA[2] = fma2(xdA, w1.x, uA[2]); uA[3] = fma2(xdA, w1.y, uA[3]);
                    uA[4] = fma2(xdA, w2.x, uA[4]); uA[5] = fma2(xdA, w2.y, uA[5]);
                    uA[6] = fma2(xdA, w3.x, uA[6]); uA[7] = fma2(xdA, w3.y, uA[7]);
                    uB[0] = fma2(xdB, w0.x, uB[0]); uB[1] = fma2(xdB, w0.y, uB[1]);
                    uB[2] = fma2(xdB, w1.x, uB[2]); uB[3] = fma2(xdB, w1.y, uB[3]);
                    uB[4] = fma2(xdB, w2.x, uB[4]); uB[5] = fma2(xdB, w2.y, uB[5]);
                    uB[6] = fma2(xdB, w3.x, uB[6]); uB[7] = fma2(xdB, w3.y, uB[7]);
                }
            }

            if (FIRST) {
#pragma unroll
                for (int k = 0; k < 8; k++) {
                    accA[k] = add2(accA[k], uA[k]);
                    accB[k] = add2(accB[k], uB[k]);
                }
            } else {
                u64 lA = mul2(uA[0], vsA[0]);
                u64 lB = mul2(uB[0], vsB[0]);
#pragma unroll
                for (int k = 1; k < 8; k++) {
                    lA = fma2(uA[k], vsA[k], lA);
                    lB = fma2(uB[k], vsB[k], lB);
                }
                const float wA = __expf(hadd2(lA));  // logits O(10): no max-shift needed
                const float wB = __expf(hadd2(lB));
                const u64 wdA = dup2(wA);
                const u64 wdB = dup2(wB);
#pragma unroll
                for (int k = 0; k < 8; k++) {
                    accA[k] = fma2(wdA, uA[k], accA[k]);
                    accB[k] = fma2(wdB, uB[k], accB[k]);
                }
                accdA += wA;
                accdB += wB;
            }
        }
        __syncthreads();   // all warps done with buf[s&1] before refill at s+1
    }

    ulonglong2* ppA = reinterpret_cast<ulonglong2*>(&g_partial[blockIdx.x][bA][n][0]);
    ppA[0] = make_ulonglong2(accA[0], accA[1]);
    ppA[1] = make_ulonglong2(accA[2], accA[3]);
    ppA[2] = make_ulonglong2(accA[4], accA[5]);
    ppA[3] = make_ulonglong2(accA[6], accA[7]);
    ulonglong2* ppB = reinterpret_cast<ulonglong2*>(&g_partial[blockIdx.x][bB][n][0]);
    ppB[0] = make_ulonglong2(accB[0], accB[1]);
    ppB[1] = make_ulonglong2(accB[2], accB[3]);
    ppB[2] = make_ulonglong2(accB[4], accB[5]);
    ppB[3] = make_ulonglong2(accB[6], accB[7]);
    g_pden[blockIdx.x][bA][n] = FIRST ? (float)CI : accdA;
    g_pden[blockIdx.x][bB][n] = FIRST ? (float)CI : accdB;
}

// ---- Reduce partials, squash, update Vsum / write output ----
template <bool FIRST, bool LAST>
__global__ void __launch_bounds__(NOUT * DOUT)
squash_update(float* __restrict__ out)
{
    const int b = blockIdx.x;
    const int tid = threadIdx.x;
    const int n = tid >> 4;
    const int d = tid & 15;

    float num = 0.0f;
#pragma unroll
    for (int c = 0; c < NCHUNK; c++) num += g_partial[c][b][n][d];
    float den = 0.0f;
#pragma unroll
    for (int c = 0; c < NCHUNK; c++) den += g_pden[c][b][n];

    const float s = num / den;

    float s2 = s * s;
#pragma unroll
    for (int off = 8; off; off >>= 1) s2 += __shfl_xor_sync(0xffffffffu, s2, off);

    const float scale = s2 / (1.0f + s2) * rsqrtf(s2 + 1e-7f);
    const float v = scale * s;

    if (LAST)       out[((size_t)b * NOUT + n) * DOUT + d] = v;
    else if (FIRST) g_vsum[b][n][d] = v;
    else            g_vsum[b][n][d] += v;
}

extern "C" void kernel_launch(void* const* d_in, const int* in_sizes, int n_in,
                              void* d_out, int out_size)
{
    const float* x;
    const float* W;
    if (in_sizes[0] == BATCH * NIN * DIN) { x = (const float*)d_in[0]; W = (const float*)d_in[1]; }
    else                                  { x = (const float*)d_in[1]; W = (const float*)d_in[0]; }
    float* out = (float*)d_out;

    static bool attr_done = false;
    if (!attr_done) {
        cudaFuncSetAttribute(route_pass<true >, cudaFuncAttributeMaxDynamicSharedMemorySize, SMEM_BYTES);
        cudaFuncSetAttribute(route_pass<false>, cudaFuncAttributeMaxDynamicSharedMemorySize, SMEM_BYTES);
        attr_done = true;
    }

    prep<<<XT_BLOCKS + WT_BLOCKS, 256>>>(x, W);

    dim3 grid(NCHUNK, BTILES);
    const int threads = 320;

    route_pass<true ><<<grid, threads, SMEM_BYTES>>>();
    squash_update<true , false><<<BATCH, NOUT * DOUT>>>(out);

    route_pass<false><<<grid, threads, SMEM_BYTES>>>();
    squash_update<false, false><<<BATCH, NOUT * DOUT>>>(out);

    route_pass<false><<<grid, threads, SMEM_BYTES>>>();   // <- ncu capture slot (launch #5)
    squash_update<false, true ><<<BATCH, NOUT * DOUT>>>(out);
}

// round 6
// speedup vs baseline: 1.1629x; 1.0630x over previous
#include <cuda_runtime.h>

#define BATCH 1024
#define NIN   1152
#define DIN   8
#define NOUT  10
#define DOUT  16
#define QTOT  (NIN * DIN)        // 9216
#define NCHUNK 36
#define CI     (NIN / NCHUNK)    // 32 input capsules per block
#define TB     32                // batches per CTA (2 per thread, 16 lanes x 2 dhalf)
#define BTILES (BATCH / TB)      // 32
#define SI     4                 // i's per W sub-tile
#define NSUB   (CI / SI)         // 8

#define WS_FLOATS (SI * NOUT * 128)      // 5120 floats per W buffer (20KB)
#define XS_FLOATS (CI * DIN * TB)        // 8192 floats (32KB)
#define SMEM_BYTES ((2 * WS_FLOATS + XS_FLOATS) * 4)   // 72KB

typedef unsigned long long u64;

// Static device scratch (no allocations allowed)
__device__ float g_xt[QTOT][BATCH];                     // x^T: [i*8+e][b]
__device__ float g_Wt[NIN * NOUT * DIN * DOUT];         // W^T: [i][n][e][d]
__device__ float g_partial[NCHUNK][BATCH][NOUT][DOUT];
__device__ float g_pden[NCHUNK][BATCH][NOUT];
__device__ float g_vsum[BATCH][NOUT][DOUT];

// ---- packed f32x2 helpers ----
__device__ __forceinline__ u64 fma2(u64 a, u64 b, u64 c) {
    u64 d; asm("fma.rn.f32x2 %0,%1,%2,%3;" : "=l"(d) : "l"(a), "l"(b), "l"(c)); return d;
}
__device__ __forceinline__ u64 mul2(u64 a, u64 b) {
    u64 d; asm("mul.rn.f32x2 %0,%1,%2;" : "=l"(d) : "l"(a), "l"(b)); return d;
}
__device__ __forceinline__ u64 add2(u64 a, u64 b) {
    u64 d; asm("add.rn.f32x2 %0,%1,%2;" : "=l"(d) : "l"(a), "l"(b)); return d;
}
__device__ __forceinline__ u64 dup2(float x) {
    u64 d; asm("mov.b64 %0,{%1,%1};" : "=l"(d) : "f"(x)); return d;
}
__device__ __forceinline__ float hadd2(u64 a) {
    float lo, hi; asm("mov.b64 {%0,%1},%2;" : "=f"(lo), "=f"(hi) : "l"(a)); return lo + hi;
}

// ---- cp.async helpers ----
__device__ __forceinline__ void cpa16(void* smem_dst, const void* gmem_src) {
    unsigned s = (unsigned)__cvta_generic_to_shared(smem_dst);
    asm volatile("cp.async.cg.shared.global [%0], [%1], 16;" :: "r"(s), "l"(gmem_src));
}
__device__ __forceinline__ void cpa_commit() { asm volatile("cp.async.commit_group;"); }
template <int N> __device__ __forceinline__ void cpa_wait() {
    asm volatile("cp.async.wait_group %0;" :: "n"(N));
}

// ---- fused prep: x[b][q] -> g_xt[q][b]  AND  W[in][d][e] -> g_Wt[in][e][d] ----
#define XT_BLOCKS (QTOT / 32 * (BATCH / 32))
#define WT_BLOCKS 720
__global__ void prep(const float* __restrict__ x, const float* __restrict__ W)
{
    if (blockIdx.x < XT_BLOCKS) {
        __shared__ float t[32][33];
        const int tile = blockIdx.x;
        const int q0 = (tile % (QTOT / 32)) * 32;
        const int b0 = (tile / (QTOT / 32)) * 32;
        const int lane = threadIdx.x & 31;
        const int w = threadIdx.x >> 5;
#pragma unroll
        for (int r = w; r < 32; r += 8)
            t[r][lane] = x[(size_t)(b0 + r) * QTOT + q0 + lane];
        __syncthreads();
#pragma unroll
        for (int r = w; r < 32; r += 8)
            g_xt[q0 + r][b0 + lane] = t[lane][r];
    } else {
        const int wb = blockIdx.x - XT_BLOCKS;
#pragma unroll
        for (int k = 0; k < 8; k++) {
            const int g = wb * 2048 + k * 256 + threadIdx.x;
            const int d = g & 15;
            const int e = (g >> 4) & 7;
            const int in = g >> 7;
            g_Wt[g] = W[(size_t)in * 128 + d * 8 + e];
        }
    }
}

// ---- One routing pass ----
// warp = output capsule n. lane = dh*16 + bl: thread owns batches (bl, bl+16)
// restricted to d-range [dh*8, dh*8+8) (4 f32x2 pairs). Logit completed via
// one shfl_xor(16) per batch per i. Data regs halved vs 2-batch-full-d ->
// 2 CTAs/SM resident.
template <bool FIRST>
__global__ void __launch_bounds__(320, 2)
route_pass()
{
    extern __shared__ float sm[];
    float* ws0 = sm;                       // W buffers [2][SI*NOUT*128]
    float* xs  = sm + 2 * WS_FLOATS;       // x tile [CI*8][TB=32]

    const int tid  = threadIdx.x;
    const int n    = tid >> 5;
    const int lane = tid & 31;
    const int dh   = lane >> 4;            // d-half 0/1
    const int bl   = lane & 15;            // batch-lane 0..15
    const int bA   = blockIdx.y * TB + bl;
    const int bB   = bA + 16;
    const int i0   = blockIdx.x * CI;

    // ---- stage x tile: 256 rows x 32 floats = 2048 x 16B chunks ----
    {
        const float* src0 = &g_xt[i0 * DIN][0] + blockIdx.y * TB;
#pragma unroll
        for (int k = 0; k < 7; k++) {
            const int idx = tid + k * 320;
            if (idx < (CI * DIN) * (TB / 4)) {
                const int row = idx >> 3, off = idx & 7;   // 8 chunks per 32-float row
                cpa16(xs + row * TB + off * 4,
                      src0 + (size_t)row * BATCH + off * 4);
            }
        }
    }
    // ---- prefetch W sub-tile 0 ----
    const float* __restrict__ wbase = g_Wt + (size_t)i0 * NOUT * 128;
#pragma unroll
    for (int k = 0; k < 4; k++)
        cpa16(ws0 + (tid + k * 320) * 4, wbase + (size_t)(tid + k * 320) * 4);
    cpa_commit();

    u64 vsA[4], vsB[4];
    if (!FIRST) {
        const ulonglong2* vpA = reinterpret_cast<const ulonglong2*>(&g_vsum[bA][n][dh * 8]);
        const ulonglong2* vpB = reinterpret_cast<const ulonglong2*>(&g_vsum[bB][n][dh * 8]);
        ulonglong2 tA0 = vpA[0], tA1 = vpA[1];
        ulonglong2 tB0 = vpB[0], tB1 = vpB[1];
        vsA[0] = tA0.x; vsA[1] = tA0.y; vsA[2] = tA1.x; vsA[3] = tA1.y;
        vsB[0] = tB0.x; vsB[1] = tB0.y; vsB[2] = tB1.x; vsB[3] = tB1.y;
    }

    u64 accA[4], accB[4];
#pragma unroll
    for (int k = 0; k < 4; k++) { accA[k] = 0ull; accB[k] = 0ull; }
    float accdA = 0.0f, accdB = 0.0f;

    for (int s = 0; s < NSUB; s++) {
        if (s + 1 < NSUB) {
            float* dst = ws0 + ((s + 1) & 1) * WS_FLOATS;
            const float* src = wbase + (size_t)(s + 1) * WS_FLOATS;
#pragma unroll
            for (int k = 0; k < 4; k++)
                cpa16(dst + (tid + k * 320) * 4, src + (size_t)(tid + k * 320) * 4);
            cpa_commit();
            cpa_wait<1>();
        } else {
            cpa_wait<0>();
        }
        __syncthreads();

        const float* __restrict__ wsb = ws0 + (s & 1) * WS_FLOATS;
        const float* __restrict__ xsb = xs + s * SI * DIN * TB;

        for (int ii = 0; ii < SI; ii++) {
            // W base for (ii, n), this thread's d-half
            const float* __restrict__ wp = wsb + (ii * NOUT + n) * 128 + dh * 8;

            u64 uA[4], uB[4];
#pragma unroll
            for (int e = 0; e < 8; e++) {
                const float xa = xsb[(ii * DIN + e) * TB + bl];
                const float xb = xsb[(ii * DIN + e) * TB + bl + 16];
                const u64 xdA = dup2(xa);
                const u64 xdB = dup2(xb);
                const ulonglong2 w01 = *reinterpret_cast<const ulonglong2*>(wp + e * 16);
                const ulonglong2 w23 = *reinterpret_cast<const ulonglong2*>(wp + e * 16 + 4);
                if (e == 0) {
                    uA[0] = mul2(xdA, w01.x); uA[1] = mul2(xdA, w01.y);
                    uA[2] = mul2(xdA, w23.x); uA[3] = mul2(xdA, w23.y);
                    uB[0] = mul2(xdB, w01.x); uB[1] = mul2(xdB, w01.y);
                    uB[2] = mul2(xdB, w23.x); uB[3] = mul2(xdB, w23.y);
                } else {
                    uA[0] = fma2(xdA, w01.x, uA[0]); uA[1] = fma2(xdA, w01.y, uA[1]);
                    uA[2] = fma2(xdA, w23.x, uA[2]); uA[3] = fma2(xdA, w23.y, uA[3]);
                    uB[0] = fma2(xdB, w01.x, uB[0]); uB[1] = fma2(xdB, w01.y, uB[1]);
                    uB[2] = fma2(xdB, w23.x, uB[2]); uB[3] = fma2(xdB, w23.y, uB[3]);
                }
            }

            if (FIRST) {
#pragma unroll
                for (int k = 0; k < 4; k++) {
                    accA[k] = add2(accA[k], uA[k]);
                    accB[k] = add2(accB[k], uB[k]);
                }
            } else {
                // half-logit for this d-half, then combine across dh via shfl
                u64 lA2 = mul2(uA[0], vsA[0]);
                u64 lB2 = mul2(uB[0], vsB[0]);
#pragma unroll
                for (int k = 1; k < 4; k++) {
                    lA2 = fma2(uA[k], vsA[k], lA2);
                    lB2 = fma2(uB[k], vsB[k], lB2);
                }
                float lA = hadd2(lA2);
                float lB = hadd2(lB2);
                lA += __shfl_xor_sync(0xffffffffu, lA, 16);
                lB += __shfl_xor_sync(0xffffffffu, lB, 16);
                const float wA = __expf(lA);   // logits O(10): no max-shift needed
                const float wB = __expf(lB);
                const u64 wdA = dup2(wA);
                const u64 wdB = dup2(wB);
#pragma unroll
                for (int k = 0; k < 4; k++) {
                    accA[k] = fma2(wdA, uA[k], accA[k]);
                    accB[k] = fma2(wdB, uB[k], accB[k]);
                }
                accdA += wA;
                accdB += wB;
            }
        }
        __syncthreads();   // all warps done with buf[s&1] before refill at s+1
    }

    ulonglong2* ppA = reinterpret_cast<ulonglong2*>(&g_partial[blockIdx.x][bA][n][dh * 8]);
    ppA[0] = make_ulonglong2(accA[0], accA[1]);
    ppA[1] = make_ulonglong2(accA[2], accA[3]);
    ulonglong2* ppB = reinterpret_cast<ulonglong2*>(&g_partial[blockIdx.x][bB][n][dh * 8]);
    ppB[0] = make_ulonglong2(accB[0], accB[1]);
    ppB[1] = make_ulonglong2(accB[2], accB[3]);
    if (!FIRST && dh == 0) {
        g_pden[blockIdx.x][bA][n] = accdA;
        g_pden[blockIdx.x][bB][n] = accdB;
    }
}

// ---- Reduce partials, squash, update Vsum / write output ----
template <bool FIRST, bool LAST>
__global__ void __launch_bounds__(NOUT * DOUT)
squash_update(float* __restrict__ out)
{
    const int b = blockIdx.x;
    const int tid = threadIdx.x;
    const int n = tid >> 4;
    const int d = tid & 15;

    float num = 0.0f;
#pragma unroll
    for (int c = 0; c < NCHUNK; c++) num += g_partial[c][b][n][d];

    float den;
    if (FIRST) {
        den = (float)NIN;          // uniform weights on pass 0
    } else {
        den = 0.0f;
#pragma unroll
        for (int c = 0; c < NCHUNK; c++) den += g_pden[c][b][n];
    }

    const float s = num / den;

    float s2 = s * s;
#pragma unroll
    for (int off = 8; off; off >>= 1) s2 += __shfl_xor_sync(0xffffffffu, s2, off);

    const float scale = s2 / (1.0f + s2) * rsqrtf(s2 + 1e-7f);
    const float v = scale * s;

    if (LAST)       out[((size_t)b * NOUT + n) * DOUT + d] = v;
    else if (FIRST) g_vsum[b][n][d] = v;
    else            g_vsum[b][n][d] += v;
}

extern "C" void kernel_launch(void* const* d_in, const int* in_sizes, int n_in,
                              void* d_out, int out_size)
{
    const float* x;
    const float* W;
    if (in_sizes[0] == BATCH * NIN * DIN) { x = (const float*)d_in[0]; W = (const float*)d_in[1]; }
    else                                  { x = (const float*)d_in[1]; W = (const float*)d_in[0]; }
    float* out = (float*)d_out;

    static bool attr_done = false;
    if (!attr_done) {
        cudaFuncSetAttribute(route_pass<true >, cudaFuncAttributeMaxDynamicSharedMemorySize, SMEM_BYTES);
        cudaFuncSetAttribute(route_pass<false>, cudaFuncAttributeMaxDynamicSharedMemorySize, SMEM_BYTES);
        attr_done = true;
    }

    prep<<<XT_BLOCKS + WT_BLOCKS, 256>>>(x, W);

    dim3 grid(NCHUNK, BTILES);
    const int threads = 320;

    route_pass<true ><<<grid, threads, SMEM_BYTES>>>();
    squash_update<true , false><<<BATCH, NOUT * DOUT>>>(out);

    route_pass<false><<<grid, threads, SMEM_BYTES>>>();
    squash_update<false, false><<<BATCH, NOUT * DOUT>>>(out);

    route_pass<false><<<grid, threads, SMEM_BYTES>>>();   // <- ncu capture slot (launch #5)
    squash_update<false, true ><<<BATCH, NOUT * DOUT>>>(out);
}